// round 14
// baseline (speedup 1.0000x reference)
#include <cuda_runtime.h>

#define N 768
#define D 512
#define NCAND ((N * (N - 1)) / 2)     // 294528 candidate i<j pairs
#define B2 592
#define T2 256
#define CPW 64                        // candidates per warp (2 rounds of 32)

// Scratch (no allocations allowed anywhere). Zero-initialized at load.
__device__ double g_part[B2];
__device__ int    g_pcnt[B2];
__device__ int    g_done;             // reset by the finishing block each replay

__device__ __forceinline__ float fast_rcp(float x) {
    float r; asm("rcp.approx.f32 %0, %1;" : "=f"(r) : "f"(x)); return r;
}
__device__ __forceinline__ float fast_lg2(float x) {
    float r; asm("lg2.approx.f32 %0, %1;" : "=f"(r) : "f"(x)); return r;
}
__device__ __forceinline__ float fast_sqrt(float x) {
    float r; asm("sqrt.approx.f32 %0, %1;" : "=f"(r) : "f"(x)); return r;
}

// C(i) = number of i<j pairs with first index < i
__device__ __forceinline__ int trih(int i) { return (i * (2 * N - 1 - i)) >> 1; }

// ---------------------------------------------------------------------------
// Single kernel: candidate screening + on-the-fly MLS + last-block finish.
// No unbounded loops anywhere.
// ---------------------------------------------------------------------------
__global__ void __launch_bounds__(T2, 4)
mls_all(const float* __restrict__ muX,
        const float* __restrict__ lss,
        const void*  __restrict__ gty,
        float* __restrict__ out) {
    __shared__ double wsum[T2 / 32];
    __shared__ int    wcnt[T2 / 32];
    __shared__ int    sh_last;

    int t    = threadIdx.x;
    int lane = t & 31;
    int wid  = t >> 5;
    int gwarp = blockIdx.x * (T2 / 32) + wid;

    // ---- label width detection (int64 vs int32), block-cooperative ----
    // gty values in [0,64). If little-endian int64, every odd 32-bit word of
    // the first N words is 0. Reading word 2*j (<= 1534) is in-bounds for the
    // int64 layout; N words are in-bounds for int32.
    const int* gw = (const int*)gty;
    int flag = 0;
    #pragma unroll
    for (int k = 0; k < 3; k++) {
        int x = t + (k << 8);
        if ((x & 1) && __ldg(&gw[x]) != 0) flag = 1;
    }
    int is32 = __syncthreads_or(flag);

    float  accd = 0.0f;   // sum of d^2 / s
    float  accl = 0.0f;   // sum of lg2(prod s)
    int    mycnt = 0;

    int c0 = gwarp * CPW;
    #pragma unroll
    for (int r = 0; r < 2; r++) {
        int c = c0 + r * 32 + lane;
        bool m = false;
        int pi = 0, pj = 0;
        if (c < NCAND) {
            // decode c -> (i, j), i<j: closed form + BOUNDED fix-up.
            // disc is an exact integer < 2^24 so fp32 sqrt is off by <= 1 ulp;
            // the estimate of i is off by at most 1-2 -> 3 predicated steps.
            float disc = (float)((2 * N - 1) * (2 * N - 1) - 8 * c);
            int i = (int)(((float)(2 * N - 1) - fast_sqrt(disc)) * 0.5f);
            if (i < 0) i = 0;
            if (i > N - 2) i = N - 2;
            #pragma unroll
            for (int f = 0; f < 3; f++) {
                if (i > 0 && trih(i) > c) --i;
                else if (i < N - 2 && trih(i + 1) <= c) ++i;
            }
            int j = i + 1 + (c - trih(i));
            int li = is32 ? __ldg(&gw[i]) : __ldg(&gw[2 * i]);
            int lj = is32 ? __ldg(&gw[j]) : __ldg(&gw[2 * j]);
            m = (li == lj) && (j > i) && (j < N);
            pi = i; pj = j;
        }
        unsigned bal = __ballot_sync(0xFFFFFFFFu, m);
        mycnt += __popc(bal);
        while (bal) {                       // bounded: <= 32 iterations
            int src = __ffs(bal) - 1;
            bal &= bal - 1;
            int i = __shfl_sync(0xFFFFFFFFu, pi, src);
            int j = __shfl_sync(0xFFFFFFFFu, pj, src);

            const float4* mi = (const float4*)(muX + (size_t)i * D);
            const float4* mj = (const float4*)(muX + (size_t)j * D);
            const float4* si = (const float4*)(lss + (size_t)i * D);
            const float4* sj = (const float4*)(lss + (size_t)j * D);

            // load both mu rows (this lane's 4 float4 per row); norms on the fly
            float4 va[4], vb[4];
            float ssa = 0.0f, ssb = 0.0f;
            #pragma unroll
            for (int k = 0; k < 4; k++) {
                int idx = lane + 32 * k;        // 128 float4 per row
                va[k] = mi[idx];
                vb[k] = mj[idx];
                ssa += va[k].x * va[k].x + va[k].y * va[k].y
                     + va[k].z * va[k].z + va[k].w * va[k].w;
                ssb += vb[k].x * vb[k].x + vb[k].y * vb[k].y
                     + vb[k].z * vb[k].z + vb[k].w * vb[k].w;
            }
            #pragma unroll
            for (int o = 16; o; o >>= 1) {
                ssa += __shfl_xor_sync(0xFFFFFFFFu, ssa, o);
                ssb += __shfl_xor_sync(0xFFFFFFFFu, ssb, o);
            }
            float rna = fast_rcp(fmaxf(fast_sqrt(ssa), 1e-12f));
            float rnb = fast_rcp(fmaxf(fast_sqrt(ssb), 1e-12f));

            #pragma unroll
            for (int k = 0; k < 4; k++) {
                int idx = lane + 32 * k;
                float4 la = si[idx];
                float4 lb = sj[idx];
                float d, s, prod;
                d = va[k].x * rna - vb[k].x * rnb;
                s = __expf(la.x) + __expf(lb.x);
                accd += d * d * fast_rcp(s); prod = s;
                d = va[k].y * rna - vb[k].y * rnb;
                s = __expf(la.y) + __expf(lb.y);
                accd += d * d * fast_rcp(s); prod *= s;
                d = va[k].z * rna - vb[k].z * rnb;
                s = __expf(la.z) + __expf(lb.z);
                accd += d * d * fast_rcp(s); prod *= s;
                d = va[k].w * rna - vb[k].w * rnb;
                s = __expf(la.w) + __expf(lb.w);
                accd += d * d * fast_rcp(s); prod *= s;
                accl += fast_lg2(prod);         // 1 lg2 per 4 elements
            }
        }
    }

    // ---- warp reduce (float), block reduce (double), publish partial ----
    float val = accd + 0.69314718055994531f * accl;
    #pragma unroll
    for (int o = 16; o; o >>= 1) val += __shfl_xor_sync(0xFFFFFFFFu, val, o);
    if (lane == 0) { wsum[wid] = (double)val; wcnt[wid] = mycnt; }
    __syncthreads();
    if (t == 0) {
        double bs = 0.0;
        int    bc = 0;
        #pragma unroll
        for (int w = 0; w < T2 / 32; w++) { bs += wsum[w]; bc += wcnt[w]; }
        g_part[blockIdx.x] = bs;
        g_pcnt[blockIdx.x] = bc;
        // acq_rel arrival: release orders our partial stores before the
        // arrival; acquire makes earlier blocks' partials visible if we are
        // last. Returns the old count.
        int old;
        asm volatile("atom.acq_rel.gpu.global.add.s32 %0, [%1], %2;"
                     : "=r"(old) : "l"(&g_done), "r"(1) : "memory");
        sh_last = (old == B2 - 1) ? 1 : 0;
    }
    __syncthreads();

    // ---- LAST-ARRIVING block: deterministic final reduction + reset ----
    if (sh_last) {
        double a2 = 0.0;
        int    c2 = 0;
        for (int i = t; i < B2; i += T2) {     // bounded: 3 iterations
            a2 += __ldcg(&g_part[i]);
            c2 += __ldcg(&g_pcnt[i]);
        }
        #pragma unroll
        for (int o = 16; o; o >>= 1) {
            a2 += __shfl_xor_sync(0xFFFFFFFFu, a2, o);
            c2 += __shfl_xor_sync(0xFFFFFFFFu, c2, o);
        }
        if (lane == 0) { wsum[wid] = a2; wcnt[wid] = c2; }
        __syncthreads();
        if (t == 0) {
            double s = 0.0;
            int    c = 0;
            #pragma unroll
            for (int w = 0; w < T2 / 32; w++) { s += wsum[w]; c += wcnt[w]; }
            out[0] = c ? (float)(s / (double)c) : 0.0f;
            g_done = 0;                  // reset for next graph replay
        }
    }
}

extern "C" void kernel_launch(void* const* d_in, const int* in_sizes, int n_in,
                              void* d_out, int out_size) {
    const float* muX = (const float*)d_in[0];
    const float* lss = (const float*)d_in[1];
    const void*  gty = d_in[2];
    (void)in_sizes; (void)n_in; (void)out_size;

    mls_all<<<B2, T2>>>(muX, lss, gty, (float*)d_out);
}

// round 15
// speedup vs baseline: 1.1215x; 1.1215x over previous
#include <cuda_runtime.h>

#define N 768
#define D 512
#define MAXP ((N * (N - 1)) / 2)
#define B2 592
#define T2 256
#define NW2 (B2 * T2 / 32)            // 4736 warps in K2

// Scratch (no allocations allowed anywhere). Zero-initialized at load.
__device__ int    g_pairs[MAXP];
__device__ double g_part[B2];
__device__ int    g_cnt;              // pair count; reset by K2's finisher
__device__ int    g_done;

__device__ __forceinline__ float fast_rcp(float x) {
    float r; asm("rcp.approx.f32 %0, %1;" : "=f"(r) : "f"(x)); return r;
}
__device__ __forceinline__ float fast_lg2(float x) {
    float r; asm("lg2.approx.f32 %0, %1;" : "=f"(r) : "f"(x)); return r;
}
__device__ __forceinline__ float fast_sqrt(float x) {
    float r; asm("sqrt.approx.f32 %0, %1;" : "=f"(r) : "f"(x)); return r;
}

// ---------------------------------------------------------------------------
// K1: pair generation ONLY (labels; 3KB of reads). One block per row.
//     Shared-memory compaction; ONE global atomic per block.
// ---------------------------------------------------------------------------
__global__ void __launch_bounds__(128)
pairgen_kernel(const void* __restrict__ gty) {
    __shared__ int s_n;
    __shared__ int s_base;
    __shared__ int s_list[N];

    int row = blockIdx.x;
    int t   = threadIdx.x;

    // Label width detection (int64 vs int32): values in [0,64). If little-
    // endian int64, every odd 32-bit word of the first N words is 0. Word
    // index 2*j <= 1534 is in-bounds for int64; N words in-bounds for int32.
    const int* gw = (const int*)gty;
    int flag = 0;
    if (t == 0) s_n = 0;
    #pragma unroll
    for (int k = 0; k < 6; k++) {
        int x = t + (k << 7);
        if ((x & 1) && __ldg(&gw[x]) != 0) flag = 1;
    }
    int is32 = __syncthreads_or(flag);

    int li = is32 ? __ldg(&gw[row]) : __ldg(&gw[2 * row]);
    #pragma unroll
    for (int k = 0; k < 6; k++) {
        int j = t + (k << 7);
        if (j > row && (is32 ? __ldg(&gw[j]) : __ldg(&gw[2 * j])) == li)
            s_list[atomicAdd(&s_n, 1)] = (row << 16) | j;
    }
    __syncthreads();
    if (t == 0) s_base = s_n ? atomicAdd(&g_cnt, s_n) : 0;
    __syncthreads();
    for (int p = t; p < s_n; p += 128)
        g_pairs[s_base + p] = s_list[p];
}

// ---------------------------------------------------------------------------
// K2: one warp per pair (balanced), on-the-fly normalize + exp, grouped lg2,
//     last-arriving-block finish (no spin loops).
// ---------------------------------------------------------------------------
__global__ void __launch_bounds__(T2)
mls_kernel(const float* __restrict__ muX,
           const float* __restrict__ lss,
           float* __restrict__ out) {
    __shared__ double wsum[T2 / 32];
    __shared__ int    sh_last;

    int t    = threadIdx.x;
    int lane = t & 31;
    int wid  = t >> 5;
    int gwarp = blockIdx.x * (T2 / 32) + wid;
    int np = g_cnt;

    float accd = 0.0f;   // sum of d^2 / s
    float accl = 0.0f;   // sum of lg2(prod s)
    for (int p = gwarp; p < np; p += NW2) {
        int pk = g_pairs[p];
        int pi = pk >> 16;
        int pj = pk & 0xFFFF;
        const float4* mi = (const float4*)(muX + (size_t)pi * D);
        const float4* mj = (const float4*)(muX + (size_t)pj * D);
        const float4* si = (const float4*)(lss + (size_t)pi * D);
        const float4* sj = (const float4*)(lss + (size_t)pj * D);

        // Load both raw mu rows (4 float4 per lane per row); norms on the fly.
        float4 va[4], vb[4];
        float ssa = 0.0f, ssb = 0.0f;
        #pragma unroll
        for (int k = 0; k < 4; k++) {
            int idx = lane + 32 * k;          // 128 float4 per row
            va[k] = mi[idx];
            vb[k] = mj[idx];
            ssa += va[k].x * va[k].x + va[k].y * va[k].y
                 + va[k].z * va[k].z + va[k].w * va[k].w;
            ssb += vb[k].x * vb[k].x + vb[k].y * vb[k].y
                 + vb[k].z * vb[k].z + vb[k].w * vb[k].w;
        }
        #pragma unroll
        for (int o = 16; o; o >>= 1) {
            ssa += __shfl_xor_sync(0xFFFFFFFFu, ssa, o);
            ssb += __shfl_xor_sync(0xFFFFFFFFu, ssb, o);
        }
        float rna = fast_rcp(fmaxf(fast_sqrt(ssa), 1e-12f));
        float rnb = fast_rcp(fmaxf(fast_sqrt(ssb), 1e-12f));

        #pragma unroll
        for (int k = 0; k < 4; k++) {
            int idx = lane + 32 * k;
            float4 la = si[idx];
            float4 lb = sj[idx];
            float d, s, prod;
            d = va[k].x * rna - vb[k].x * rnb;
            s = __expf(la.x) + __expf(lb.x);
            accd += d * d * fast_rcp(s); prod = s;
            d = va[k].y * rna - vb[k].y * rnb;
            s = __expf(la.y) + __expf(lb.y);
            accd += d * d * fast_rcp(s); prod *= s;
            d = va[k].z * rna - vb[k].z * rnb;
            s = __expf(la.z) + __expf(lb.z);
            accd += d * d * fast_rcp(s); prod *= s;
            d = va[k].w * rna - vb[k].w * rnb;
            s = __expf(la.w) + __expf(lb.w);
            accd += d * d * fast_rcp(s); prod *= s;
            accl += fast_lg2(prod);           // 1 lg2 per 4 elements
        }
    }

    // warp reduce (float), block reduce (double), publish partial
    float val = accd + 0.69314718055994531f * accl;
    #pragma unroll
    for (int o = 16; o; o >>= 1) val += __shfl_xor_sync(0xFFFFFFFFu, val, o);
    if (lane == 0) wsum[wid] = (double)val;
    __syncthreads();
    if (t == 0) {
        double bs = 0.0;
        #pragma unroll
        for (int w = 0; w < T2 / 32; w++) bs += wsum[w];
        g_part[blockIdx.x] = bs;
        // acq_rel arrival: release orders our partial store; acquire makes
        // earlier blocks' partials visible if we are last. Returns old count.
        int old;
        asm volatile("atom.acq_rel.gpu.global.add.s32 %0, [%1], %2;"
                     : "=r"(old) : "l"(&g_done), "r"(1) : "memory");
        sh_last = (old == B2 - 1) ? 1 : 0;
    }
    __syncthreads();

    // LAST-ARRIVING block: deterministic final reduction + counter resets.
    if (sh_last) {
        double a2 = 0.0;
        for (int i = t; i < B2; i += T2)      // bounded: 3 iterations
            a2 += __ldcg(&g_part[i]);
        #pragma unroll
        for (int o = 16; o; o >>= 1) a2 += __shfl_xor_sync(0xFFFFFFFFu, a2, o);
        if (lane == 0) wsum[wid] = a2;
        __syncthreads();
        if (t == 0) {
            double s = 0.0;
            #pragma unroll
            for (int w = 0; w < T2 / 32; w++) s += wsum[w];
            out[0] = np ? (float)(s / (double)np) : 0.0f;
            g_done = 0;                  // reset for next graph replay
            g_cnt  = 0;
        }
    }
}

extern "C" void kernel_launch(void* const* d_in, const int* in_sizes, int n_in,
                              void* d_out, int out_size) {
    const float* muX = (const float*)d_in[0];
    const float* lss = (const float*)d_in[1];
    const void*  gty = d_in[2];
    (void)in_sizes; (void)n_in; (void)out_size;

    pairgen_kernel<<<N, 128>>>(gty);
    mls_kernel<<<B2, T2>>>(muX, lss, (float*)d_out);
}